// round 15
// baseline (speedup 1.0000x reference)
#include <cuda_runtime.h>
#include <cuda_fp16.h>

typedef unsigned int uint;
typedef unsigned short ushort;

#define NTHR 384
#define NCTA 128
#define SEG_U2 4096u            // B segment (K=512): [4 nt][32 ks][32 lane] uint2

// SMEM layout (bytes)
#define SA0_OFF 0               // L0 x+h0 weights [64 ks][2 mt][32 ln] uint4 = 65536
#define SA1_OFF 65536           // L1 h0cat weights (64 ks)                  = 65536
#define SM_OFF  131072          // M fragments (fp16) (64 ks)                = 65536
#define SR_OFF  196608          // 7 partial buffers x 1056 floats           = 29568
#define SF_OFF  226176          // smem flags (8 words), 128B region
#define SB_OFF  226304          // staged biases [3][8][4] floats
#define SMEM_BYTES (226304 + 512)

// Static device scratch (allocation-free). Counters each on own 128B line.
__device__ uint2 g_xfrag[512u * SEG_U2];          // x B-fragments per t (~16MB)
__device__ uint2 g_h0frag[4u * SEG_U2];           // [parity][dir] layer0 h
__device__ uint2 g_h1hist[513ull * 2 * SEG_U2];   // h1cat history [t+1][dir] (~34MB)
__device__ uint4 g_w1h[128ull * 2048];            // per-CTA L1 Whh fragments (4MB)
__device__ uint4 g_afc[32u * 64u * 32u];          // FC A fragments (fp16)
__device__ uint2 g_wfcB[128u * 32u * 32u];        // Wfc B-frags for M build
__device__ unsigned g_arr_p[32];                  // gridbar arrive
__device__ unsigned g_rel_p[32];                  // gridbar release
// 8 publish counters: [g*32] = h0 group g (g=0..3), [(4+g)*32] = h1 group g.
// group = cta >> 5 (32 CTAs each; groups 0,1 = fwd dir, 2,3 = bwd dir).
__device__ unsigned g_cnt_p[8 * 32];

// worker barrier: warps 0..10 (352 threads); warp 11 free-runs
#define BARW() asm volatile("bar.sync 1, 352;" ::: "memory")

// ---------------- grid barrier (prologue/epilogue only) ----------------------
__device__ __forceinline__ void gridbar() {
    __syncthreads();
    if (threadIdx.x == 0) {
        const unsigned nb = gridDim.x;
        unsigned ticket;
        asm volatile("atom.add.acq_rel.gpu.u32 %0, [%1], %2;"
                     : "=r"(ticket) : "l"(&g_arr_p[0]), "r"(1u) : "memory");
        unsigned target = ticket - (ticket % nb) + nb;
        if (ticket % nb == nb - 1u) {
            asm volatile("red.add.release.gpu.u32 [%0], %1;"
                         :: "l"(&g_rel_p[0]), "r"(nb) : "memory");
        } else {
            unsigned rel;
            do {
                asm volatile("ld.acquire.gpu.u32 %0, [%1];"
                             : "=r"(rel) : "l"(&g_rel_p[0]) : "memory");
            } while ((int)(rel - target) < 0);
        }
    }
    __syncthreads();
}

__device__ __forceinline__ void flag_set(unsigned* f, unsigned v) {
    asm volatile("st.release.cta.u32 [%0], %1;" :: "l"(f), "r"(v) : "memory");
}
__device__ __forceinline__ void flag_wait(unsigned* f, unsigned tgt) {
    unsigned v;
    do {
        asm volatile("ld.acquire.cta.u32 %0, [%1];"
                     : "=r"(v) : "l"(f) : "memory");
    } while ((int)(v - tgt) < 0);
}

// worker publish: worker barrier orders writes, then tid0 release-increment
__device__ __forceinline__ void publish_w(unsigned* cnt) {
    BARW();
    if (threadIdx.x == 0)
        asm volatile("red.add.release.gpu.u32 [%0], %1;"
                     :: "l"(cnt), "r"(1u) : "memory");
}

// ---------------- fast activations -------------------------------------------
__device__ __forceinline__ float sigf(float v) {
    return __fdividef(1.f, 1.f + __expf(-v));
}
__device__ __forceinline__ float tanhf_fast(float v) {
    float vc = fminf(fmaxf(v, -15.f), 15.f);
    float e  = __expf(-2.f * vc);
    return __fdividef(1.f - e, 1.f + e);
}

__device__ __forceinline__ uint pack2(float a, float b) {
    __half2 h = __floats2half2_rn(a, b);
    return *reinterpret_cast<uint*>(&h);
}

// ---------------- mma.sync m16n8k16 fp16 -> fp32 ------------------------------
struct Acc { float x, y, z, w; };

__device__ __forceinline__ void mma_f16(Acc& c, uint4 a, uint b0, uint b1) {
    asm volatile(
        "mma.sync.aligned.m16n8k16.row.col.f32.f16.f16.f32 "
        "{%0,%1,%2,%3}, {%4,%5,%6,%7}, {%8,%9}, {%0,%1,%2,%3};"
        : "+f"(c.x), "+f"(c.y), "+f"(c.z), "+f"(c.w)
        : "r"(a.x), "r"(a.y), "r"(a.z), "r"(a.w), "r"(b0), "r"(b1));
}

__device__ __forceinline__ void stacc1(float* r, int m0, int n0, Acc a) {
    r[m0 * 33 + n0]           = a.x;
    r[m0 * 33 + n0 + 1]       = a.y;
    r[(m0 + 8) * 33 + n0]     = a.z;
    r[(m0 + 8) * 33 + n0 + 1] = a.w;
}

// store 4 tiles (2 mtiles x 2 ntiles) of one warp into a partial buffer
__device__ __forceinline__ void stacc4(float* r, int npair, int lane,
                                       Acc c00, Acc c01, Acc c10, Acc c11) {
    const int gid = lane >> 2, tig = lane & 3;
    const int nb  = npair * 16 + tig * 2;
    stacc1(r, gid,      nb,     c00);
    stacc1(r, gid,      nb + 8, c01);
    stacc1(r, 16 + gid, nb,     c10);
    stacc1(r, 16 + gid, nb + 8, c11);
}

// 16-kstep MMA burst (2mt x 2nt, 4 acc) + stacc
__device__ __forceinline__ void mma16(const uint4* A, const uint2* B,
                                      float* rbuf, int npair, int lane) {
    Acc c00={0,0,0,0}, c01={0,0,0,0}, c10={0,0,0,0}, c11={0,0,0,0};
    #pragma unroll 8
    for (int k = 0; k < 16; ++k) {
        uint2 v0 = __ldcg(B + k * 32);
        uint2 v1 = __ldcg(B + k * 32 + 1024);
        uint4 a0 = A[k * 64];
        uint4 a1 = A[k * 64 + 32];
        mma_f16(c00, a0, v0.x, v0.y);
        mma_f16(c01, a0, v1.x, v1.y);
        mma_f16(c10, a1, v0.x, v0.y);
        mma_f16(c11, a1, v1.x, v1.y);
    }
    stacc4(rbuf, npair, lane, c00, c01, c10, c11);
}
// 32-kstep variant, A from SMEM
__device__ __forceinline__ void mma32s(const uint4* A, const uint2* B,
                                       float* rbuf, int npair, int lane) {
    Acc c00={0,0,0,0}, c01={0,0,0,0}, c10={0,0,0,0}, c11={0,0,0,0};
    #pragma unroll 8
    for (int k = 0; k < 32; ++k) {
        uint2 v0 = __ldcg(B + k * 32);
        uint2 v1 = __ldcg(B + k * 32 + 1024);
        uint4 a0 = A[k * 64];
        uint4 a1 = A[k * 64 + 32];
        mma_f16(c00, a0, v0.x, v0.y);
        mma_f16(c01, a0, v1.x, v1.y);
        mma_f16(c10, a1, v0.x, v0.y);
        mma_f16(c11, a1, v1.x, v1.y);
    }
    stacc4(rbuf, npair, lane, c00, c01, c10, c11);
}
// 32-kstep variant, A from global (Whh1)
__device__ __forceinline__ void mma32g(const uint4* A, const uint2* B,
                                       float* rbuf, int npair, int lane) {
    Acc c00={0,0,0,0}, c01={0,0,0,0}, c10={0,0,0,0}, c11={0,0,0,0};
    #pragma unroll 8
    for (int k = 0; k < 32; ++k) {
        uint2 v0 = __ldcg(B + k * 32);
        uint2 v1 = __ldcg(B + k * 32 + 1024);
        uint4 a0 = __ldg(A + k * 64);
        uint4 a1 = __ldg(A + k * 64 + 32);
        mma_f16(c00, a0, v0.x, v0.y);
        mma_f16(c01, a0, v1.x, v1.y);
        mma_f16(c10, a1, v0.x, v0.y);
        mma_f16(c11, a1, v1.x, v1.y);
    }
    stacc4(rbuf, npair, lane, c00, c01, c10, c11);
}

// gate reduce + LSTM pointwise (threads 0-255); packed 4B h store.
// Thread map: ul = tid&7 (unit), b = tid>>3 (batch).
// Sums buffers 0..4 plus optional xb (pass -1 to skip).
__device__ __forceinline__ void pointwise_g(const float* sR, const float* b4,
                                            int xb,
                                            float& creg, float& hreg,
                                            uint2* seg, int ublk)
{
    const int tid = threadIdx.x;
    const int ul = tid & 7, b = tid >> 3;
    float g4[4];
    #pragma unroll
    for (int g = 0; g < 4; ++g) {
        int m = ul * 4 + g;
        float s = b4[g];
        #pragma unroll
        for (int p = 0; p < 5; ++p) s += sR[p * 1056 + m * 33 + b];
        if (xb >= 0) s += sR[xb * 1056 + m * 33 + b];
        g4[g] = s;
    }
    float cc = sigf(g4[1]) * creg + sigf(g4[0]) * tanhf_fast(g4[2]);
    creg = cc;
    hreg = sigf(g4[3]) * tanhf_fast(cc);
    uint hh = (uint)__half_as_ushort(__float2half_rn(hreg));
    uint hi = __shfl_xor_sync(0xffffffffu, hh, 1);     // partner unit ul^1
    if ((ul & 1) == 0) {
        int nt = b >> 3, pp = ul >> 1;
        int tp = ((b & 7) << 2) | pp;
        int ks = ublk >> 1, reg = ublk & 1;
        ((uint*)seg)[(((nt * 32 + ks) * 32 + tp) << 1) + reg] = (hi << 16) | hh;
    }
}

// -----------------------------------------------------------------------------
extern "C" __global__ void __launch_bounds__(NTHR, 1)
ar_encoder_v15(const float* __restrict__ x,     // [32,512,512]
               const float* __restrict__ Wih,   // [4][2048][1024]
               const float* __restrict__ Whh,   // [4][2048][512]
               const float* __restrict__ bih,   // [4][2048]
               const float* __restrict__ bhh,   // [4][2048]
               const float* __restrict__ Wfc,   // [512][1024]
               const float* __restrict__ bfc,   // [512]
               float* __restrict__ out)
{
    extern __shared__ char smem[];
    uint4* sA0 = (uint4*)(smem + SA0_OFF);
    uint4* sA1 = (uint4*)(smem + SA1_OFF);
    uint4* sM  = (uint4*)(smem + SM_OFF);
    float* sR  = (float*)(smem + SR_OFF);
    unsigned* sFlag = (unsigned*)(smem + SF_OFF);   // [0..3]=h1 grp, [4..7]=h0 grp
    float* sBias = (float*)(smem + SB_OFF);         // [3][8][4]

    const int tid  = threadIdx.x;
    const int cta  = blockIdx.x;
    const int lane = tid & 31;
    const int wrp  = tid >> 5;
    const int gsz  = NCTA * NTHR;
    const int gtid = cta * NTHR + tid;

    const int d    = cta >> 6;
    const int ublk = cta & 63;
    const int j0   = ublk * 8;
    const int grp  = cta >> 5;           // quarter group 0..3

    if (tid < 8) sFlag[tid] = 0u;

    // ================= prologue phase 1 =====================================
    // (a) L0 weights (Wx + Wh0) -> sA0
    for (int i = tid; i < 32 * 512; i += NTHR) {
        int kp = i & 511, m = i >> 9;
        int grow = (m & 3) * 512 + j0 + (m >> 2);
        int k, ks; const float* p;
        if (kp < 256) { k = kp * 2; ks = k >> 4;
                        p = Wih + ((size_t)d * 2048 + grow) * 1024 + k; }
        else          { k = (kp - 256) * 2; ks = 32 + (k >> 4);
                        p = Whh + ((size_t)d * 2048 + grow) * 512 + k; }
        uint packed = pack2(p[0], p[1]);
        int kk = k & 15, mtile = m >> 4, mrow = m & 15;
        int tp  = ((mrow & 7) << 2) | ((kk >> 1) & 3);
        int reg = (mrow >> 3) | ((kk >> 3) << 1);
        ((uint*)sA0)[((ks * 2 + mtile) * 32 + tp) * 4 + reg] = packed;
    }
    // (b) Wp -> sA1 as TEMP A-fragments (K=512)
    for (int i = tid; i < 32 * 256; i += NTHR) {
        int kp = i & 255, m = i >> 8;
        int grow = (m & 3) * 512 + j0 + (m >> 2);
        int k = kp * 2;
        const float* p = Wih + ((size_t)d * 2048 + grow) * 1024 + 512 + k;
        uint packed = pack2(p[0], p[1]);
        int ks = k >> 4, kk = k & 15, mtile = m >> 4, mrow = m & 15;
        int tp  = ((mrow & 7) << 2) | ((kk >> 1) & 3);
        int reg = (mrow >> 3) | ((kk >> 3) << 1);
        ((uint*)sA1)[((ks * 2 + mtile) * 32 + tp) * 4 + reg] = packed;
    }
    // (c) Wfc -> B-fragments for the M GEMM
    for (uint i = gtid; i < 128u * 32u * 32u; i += gsz) {
        int ln = (int)(i & 31), ks = (int)((i >> 5) & 31), nt = (int)(i >> 10);
        int n  = nt * 8 + (ln >> 2);
        int o0 = ks * 16 + (ln & 3) * 2;
        uint2 v;
        v.x = pack2(Wfc[(size_t)o0 * 1024 + n],       Wfc[(size_t)(o0 + 1) * 1024 + n]);
        v.y = pack2(Wfc[(size_t)(o0 + 8) * 1024 + n], Wfc[(size_t)(o0 + 9) * 1024 + n]);
        g_wfcB[i] = v;
    }
    // (d) FC weights -> fp16 A fragments
    for (uint i = gtid; i < 512u * 512u; i += gsz) {
        int kp = (int)(i & 511u), row = (int)(i >> 9);
        int k = kp * 2;
        const float* p = Wfc + ((size_t)row << 10) + k;
        uint packed = pack2(p[0], p[1]);
        int rowblk = row >> 4, mrow = row & 15;
        int kstep = k >> 4, kk = k & 15;
        int tp  = ((mrow & 7) << 2) | ((kk >> 1) & 3);
        int reg = (mrow >> 3) | ((kk >> 3) << 1);
        ((uint*)g_afc)[(((rowblk * 64 + kstep) * 32) + tp) * 4 + reg] = packed;
    }
    // (e) input x -> fp16 B fragments, all t
    for (uint s = gtid; s < 512u * SEG_U2; s += gsz) {
        int ln = (int)(s & 31), ks = (int)((s >> 5) & 31), nt = (int)((s >> 10) & 3);
        int t  = (int)(s >> 12);
        int tig = ln & 3, gid = ln >> 2;
        int n = nt * 8 + gid, k0 = ks * 16 + tig * 2;
        const float* xp = x + ((size_t)n * 512 + t) * 512 + k0;
        uint2 v;
        v.x = pack2(xp[0], xp[1]);
        v.y = pack2(xp[8], xp[9]);
        g_xfrag[s] = v;
    }
    // (f) zero h0frag (both parities) + hist[0]
    {
        uint2 z = make_uint2(0, 0);
        for (uint i = gtid; i < 6u * SEG_U2; i += gsz) {
            if (i < 4u * SEG_U2) g_h0frag[i] = z;
            else                 g_h1hist[i - 4u * SEG_U2] = z;
        }
    }
    gridbar();

    // ================= prologue phase 2: M = Wp @ Wfc (fp16, hi only) =======
    {
        const int mtile = wrp & 1;
        uint* mhi = (uint*)sM;
        for (int nt = (wrp >> 1); nt < 128; nt += 6) {
            Acc c = {0, 0, 0, 0};
            const uint2* B = g_wfcB + (size_t)nt * 1024 + lane;
            const uint4* A = sA1 + mtile * 32 + lane;
            #pragma unroll 8
            for (int ks = 0; ks < 32; ++ks) {
                uint2 v = __ldcg(B + ks * 32);
                uint4 a = A[ks * 64];
                mma_f16(c, a, v.x, v.y);
            }
            int gid = lane >> 2, tig = lane & 3;
            int h = nt * 8 + tig * 2, kk = h & 15, kstep = h >> 4;
            int tp = ((gid & 7) << 2) | ((kk >> 1) & 3);
            int base = (((kstep * 2 + mtile) * 32) + tp) * 4;
            int rhib = (kk >> 3) << 1;
            mhi[base + rhib]     = pack2(c.x, c.y);
            mhi[base + rhib + 1] = pack2(c.z, c.w);
        }
    }
    __syncthreads();

    // (g) L1 weights: h0-part (64 ks) -> sA1, Whh-part (32 ks) -> g_w1h[cta]
    for (int i = tid; i < 32 * 768; i += NTHR) {
        int kp = i % 768, m = i / 768;
        int grow = (m & 3) * 512 + j0 + (m >> 2);
        int k = kp * 2; const float* p;
        if (k < 1024) p = Wih + ((size_t)(2 + d) * 2048 + grow) * 1024 + k;
        else          p = Whh + ((size_t)(2 + d) * 2048 + grow) * 512 + (k - 1024);
        uint packed = pack2(p[0], p[1]);
        int ks = k >> 4, kk = k & 15, mtile = m >> 4, mrow = m & 15;
        int tp  = ((mrow & 7) << 2) | ((kk >> 1) & 3);
        int reg = (mrow >> 3) | ((kk >> 3) << 1);
        if (ks < 64)
            ((uint*)sA1)[((ks * 2 + mtile) * 32 + tp) * 4 + reg] = packed;
        else
            ((uint*)(g_w1h + (size_t)cta * 2048))
                [(((ks - 64) * 2 + mtile) * 32 + tp) * 4 + reg] = packed;
    }

    // (h) biases (warp-uniform j), staged to SMEM
    if (tid < 256) {
        int ulw = tid >> 5, j = j0 + ulw;
        #pragma unroll
        for (int g = 0; g < 4; ++g) {
            float a0 = __ldg(bih + (size_t)d * 2048 + g * 512 + j)
                     + __ldg(bhh + (size_t)d * 2048 + g * 512 + j);
            float a1 = __ldg(bih + (size_t)(2 + d) * 2048 + g * 512 + j)
                     + __ldg(bhh + (size_t)(2 + d) * 2048 + g * 512 + j);
            int grow = g * 512 + j;
            const float* wp = Wih + ((size_t)d * 2048 + grow) * 1024 + 512;
            float p = 0.f;
            for (int o = lane; o < 512; o += 32) p += wp[o] * __ldg(bfc + o);
            #pragma unroll
            for (int s = 16; s; s >>= 1) p += __shfl_xor_sync(0xffffffffu, p, s);
            if (lane == 0) {
                sBias[(0 * 8 + ulw) * 4 + g] = a0;
                sBias[(1 * 8 + ulw) * 4 + g] = a0 + p;
                sBias[(2 * 8 + ulw) * 4 + g] = a1;
            }
        }
    }
    // zero partial buffers
    for (int i = tid; i < 7 * 1056; i += NTHR) sR[i] = 0.f;
    __syncthreads();

    // load biases with pointwise thread map
    float bA0[4], bB0[4], bA1[4];
    {
        int ul = tid & 7;
        #pragma unroll
        for (int g = 0; g < 4; ++g) {
            bA0[g] = sBias[(0 * 8 + ul) * 4 + g];
            bB0[g] = sBias[(1 * 8 + ul) * 4 + g];
            bA1[g] = sBias[(2 * 8 + ul) * 4 + g];
        }
    }

    // (i) prime xbuf[0] (buffer 5) with Wx @ x(0)
    if (wrp == 9 || wrp == 10) {
        const int np = wrp - 9;
        mma32s(sA0 + lane, g_xfrag + np * 2048 + lane, sR + 5 * 1056, np, lane);
    }
    __syncthreads();   // sA1 / sM / g_w1h / sR primed; poller splits off after this

    // ================= main loop: poller (warp 11) / workers (0-10) =========
    float creg0 = 0.f, hreg0 = 0.f, creg1 = 0.f, hreg1 = 0.f;
    const uint4* W1h = g_w1h + (size_t)cta * 2048;

    if (wrp == 11) {
        // ---- free-running sync warp: 8 independent lane state machines ----
        if (lane < 8) {
            const int g = lane & 3;
            const bool isH1 = lane < 4;
            unsigned* cnt = &g_cnt_p[(isH1 ? 4 + g : g) * 32];
            unsigned* fl  = sFlag + (isH1 ? g : 4 + g);
            int t = 0;
            while (t < 512) {
                unsigned v;
                asm volatile("ld.acquire.gpu.u32 %0, [%1];"
                             : "=r"(v) : "l"(cnt) : "memory");
                unsigned tgt = isH1 ? 32u * (uint)t : 32u * (uint)(t + 1);
                if ((int)(v - tgt) >= 0) {
                    int tn = isH1 ? (int)(v / 32u) + 1 : (int)(v / 32u);
                    flag_set(fl, (uint)tn);      // skip-ahead
                    t = tn;
                }
            }
        }
    } else {
        for (int t = 0; t < 512; ++t) {
            const int pold = t & 1, pnew = pold ^ 1;
            const uint2* histT = g_h1hist + (size_t)t * 2 * SEG_U2;
            const uint ft = (uint)(t + 1);
            const int xb = 5 + ((t + 1) & 1);    // buffer for x(t+1)

            // ---- A-window: h0(t) ----
            if (wrp < 8) {                       // late: M@h1cat(t-1)
                const int g  = wrp >> 1;
                const int np = wrp & 1;
                flag_wait(sFlag + g, ft);
                const int km = g * 16;
                mma16(sM + km * 64 + lane,
                      histT + (size_t)(km >> 5) * SEG_U2 + (km & 31) * 32
                            + np * 2048 + lane,
                      sR + g * 1056, np, lane);
            } else if (wrp < 10) {               // early: Wh0 @ h0(t-1), 32 ks
                const int np = wrp - 8;
                if (t > 0) {
                    flag_wait(sFlag + 4 + 2 * d,     (uint)t);
                    flag_wait(sFlag + 4 + 2 * d + 1, (uint)t);
                }
                mma32s(sA0 + 2048 + lane,
                       g_h0frag + (size_t)(pold * 2 + d) * SEG_U2 + np * 2048 + lane,
                       sR + 4 * 1056, np, lane);
            } else {                             // wrp 10: Wx @ x(t+1) np0
                if (t < 511)
                    mma32s(sA0 + lane,
                           g_xfrag + (size_t)(t + 1) * SEG_U2 + lane,
                           sR + xb * 1056, 0, lane);
            }
            BARW();
            if (tid < 256)
                pointwise_g(sR, t == 0 ? bA0 : bB0, 5 + (t & 1), creg0, hreg0,
                            g_h0frag + (size_t)(pnew * 2 + d) * SEG_U2, ublk);
            publish_w(&g_cnt_p[grp * 32]);       // h0 of own quarter

            // ---- B-window: h1(t) ----
            if (wrp < 8) {                       // late: W1 @ h0cat(t)
                const int g  = wrp >> 1;
                const int np = wrp & 1;
                flag_wait(sFlag + 4 + g, ft);
                const int km = g * 16;
                mma16(sA1 + km * 64 + lane,
                      g_h0frag + (size_t)(pnew * 2 + (km >> 5)) * SEG_U2
                               + (km & 31) * 32 + np * 2048 + lane,
                      sR + g * 1056, np, lane);
            } else if (wrp < 10) {               // early: Whh1 @ h1(t-1), 32 ks
                const int np = wrp - 8;
                flag_wait(sFlag + 2 * d,     ft);
                flag_wait(sFlag + 2 * d + 1, ft);
                mma32g(W1h + lane,
                       histT + (size_t)d * SEG_U2 + np * 2048 + lane,
                       sR + 4 * 1056, np, lane);
            } else {                             // wrp 10: Wx @ x(t+1) np1
                if (t < 511)
                    mma32s(sA0 + lane,
                           g_xfrag + (size_t)(t + 1) * SEG_U2 + 2048 + lane,
                           sR + xb * 1056, 1, lane);
            }
            BARW();
            if (tid < 256)
                pointwise_g(sR, bA1, -1, creg1, hreg1,
                            g_h1hist + ((size_t)(t + 1) * 2 + d) * SEG_U2, ublk);
            publish_w(&g_cnt_p[(4 + grp) * 32]); // h1 of own quarter
        }
    }

    // ================= epilogue: h_n, c_n from registers =====================
    if (tid < 256) {
        const size_t HN = 8388608ull;             // 32*512*512
        const size_t CN = HN + 65536ull;
        int ul = tid & 7, b = tid >> 3;
        int j = j0 + ul;
        out[HN + ((size_t)((0 + d) * 32 + b)) * 512 + j] = hreg0;
        out[HN + ((size_t)((2 + d) * 32 + b)) * 512 + j] = hreg1;
        out[CN + ((size_t)((0 + d) * 32 + b)) * 512 + j] = creg0;
        out[CN + ((size_t)((2 + d) * 32 + b)) * 512 + j] = creg1;
    }

    // ================= batched FC over all t =================================
    if (tid == 0) {                      // wait for ALL h1 history (4 quarters)
        #pragma unroll
        for (int g = 0; g < 4; ++g) {
            unsigned v;
            for (;;) {
                asm volatile("ld.acquire.gpu.u32 %0, [%1];"
                             : "=r"(v) : "l"(&g_cnt_p[(4 + g) * 32]) : "memory");
                if ((int)(v - 16384u) >= 0) break;
                __nanosleep(80);
            }
        }
    }
    __syncthreads();
    {
        float* sRw = sR + wrp * 528;                 // [16][33] per warp
        for (int tt = 0; tt < 4; ++tt) {
            const int t = cta + tt * 128;
            const uint2* Bbase = g_h1hist + (size_t)(t + 1) * 2 * SEG_U2;
            for (int rb = wrp; rb < 32; rb += 12) {
                const uint4* A = g_afc + (size_t)(rb * 64) * 32 + lane;
                Acc c0={0,0,0,0}, c1={0,0,0,0}, c2={0,0,0,0}, c3={0,0,0,0};
                #pragma unroll 4
                for (int ks = 0; ks < 64; ++ks) {
                    const uint2* B = Bbase + (size_t)(ks >> 5) * SEG_U2
                                   + (ks & 31) * 32 + lane;
                    uint2 v0 = __ldcg(B);
                    uint2 v1 = __ldcg(B + 1024);
                    uint2 v2 = __ldcg(B + 2048);
                    uint2 v3 = __ldcg(B + 3072);
                    uint4 a  = __ldg(A + ks * 32);
                    mma_f16(c0, a, v0.x, v0.y);
                    mma_f16(c1, a, v1.x, v1.y);
                    mma_f16(c2, a, v2.x, v2.y);
                    mma_f16(c3, a, v3.x, v3.y);
                }
                const int gid = lane >> 2, tig = lane & 3;
                stacc1(sRw, gid, 0  + tig * 2, c0);
                stacc1(sRw, gid, 8  + tig * 2, c1);
                stacc1(sRw, gid, 16 + tig * 2, c2);
                stacc1(sRw, gid, 24 + tig * 2, c3);
                __syncwarp();
                float* op = out + ((size_t)lane * 512 + t) * 512 + rb * 16;
                #pragma unroll
                for (int q = 0; q < 4; ++q) {
                    float v0 = sRw[(q*4+0) * 33 + lane] + __ldg(bfc + rb*16 + q*4+0);
                    float v1 = sRw[(q*4+1) * 33 + lane] + __ldg(bfc + rb*16 + q*4+1);
                    float v2 = sRw[(q*4+2) * 33 + lane] + __ldg(bfc + rb*16 + q*4+2);
                    float v3 = sRw[(q*4+3) * 33 + lane] + __ldg(bfc + rb*16 + q*4+3);
                    *(float4*)(op + q * 4) = make_float4(v0, v1, v2, v3);
                }
                __syncwarp();
            }
        }
    }

    // ================= reset dataflow counters for next launch ===============
    gridbar();
    if (cta == 0 && tid == 0) {
        #pragma unroll
        for (int c = 0; c < 8; ++c)
            asm volatile("st.relaxed.gpu.u32 [%0], %1;"
                         :: "l"(&g_cnt_p[c * 32]), "r"(0u) : "memory");
    }
}

extern "C" void kernel_launch(void* const* d_in, const int* in_sizes, int n_in,
                              void* d_out, int out_size) {
    (void)in_sizes; (void)n_in; (void)out_size;
    const float* x   = (const float*)d_in[0];
    const float* Wih = (const float*)d_in[2];
    const float* Whh = (const float*)d_in[3];
    const float* bih = (const float*)d_in[4];
    const float* bhh = (const float*)d_in[5];
    const float* Wfc = (const float*)d_in[6];
    const float* bfc = (const float*)d_in[7];
    cudaFuncSetAttribute(ar_encoder_v15,
                         cudaFuncAttributeMaxDynamicSharedMemorySize, SMEM_BYTES);
    ar_encoder_v15<<<NCTA, NTHR, SMEM_BYTES>>>(x, Wih, Whh, bih, bhh, Wfc, bfc,
                                               (float*)d_out);
}

// round 16
// speedup vs baseline: 1.0446x; 1.0446x over previous
#include <cuda_runtime.h>
#include <cuda_fp16.h>

typedef unsigned int uint;
typedef unsigned short ushort;

#define NTHR 384
#define NCTA 128
#define SEG_U2 4096u            // B segment (K=512): [4 nt][32 ks][32 lane] uint2

// SMEM layout (bytes)
#define SA0_OFF 0               // L0 x+h0 weights [64 ks][2 mt][32 ln] uint4 = 65536
#define SA1_OFF 65536           // L1 h0cat weights (64 ks)                  = 65536
#define SM_OFF  131072          // M fragments (fp16) (64 ks)                = 65536
#define SR_OFF  196608          // 8 partial buffers x 1056 floats           = 33792
#define SB_OFF  230400          // staged biases [3][8][4] floats
#define SMEM_BYTES (230400 + 384)

// Static device scratch (allocation-free).
__device__ uint2 g_xfrag[512u * SEG_U2];          // x B-fragments per t (~16MB)
__device__ uint2 g_h0frag[4u * SEG_U2];           // [parity][dir] layer0 h
__device__ uint2 g_h1hist[513ull * 2 * SEG_U2];   // h1cat history [t+1][dir] (~34MB)
__device__ uint4 g_w1h[128ull * 2048];            // per-CTA L1 Whh fragments (4MB)
__device__ uint4 g_afc[32u * 64u * 32u];          // FC A fragments (fp16)
__device__ uint2 g_wfcB[128u * 32u * 32u];        // Wfc B-frags for M build
__device__ unsigned g_arr_p[32];                  // gridbar arrive
__device__ unsigned g_rel_p[32];                  // gridbar release
// 16 publish counters, each on its own 128B line:
//   h0[g][q] at (g*2+q)*32 ; h1[g][q] at (8+g*2+q)*32
//   g = CTA quarter group 0..3, q = batch group 0..1.
__device__ unsigned g_cnt_p[16 * 32];

// per-batch-group barrier: group q = warps {q, q+2, ..., q+10} (192 threads)
#define BARG(q) asm volatile("bar.sync %0, 192;" :: "r"(1 + (q)) : "memory")

// ---------------- grid barrier (prologue/epilogue only) ----------------------
__device__ __forceinline__ void gridbar() {
    __syncthreads();
    if (threadIdx.x == 0) {
        const unsigned nb = gridDim.x;
        unsigned ticket;
        asm volatile("atom.add.acq_rel.gpu.u32 %0, [%1], %2;"
                     : "=r"(ticket) : "l"(&g_arr_p[0]), "r"(1u) : "memory");
        unsigned target = ticket - (ticket % nb) + nb;
        if (ticket % nb == nb - 1u) {
            asm volatile("red.add.release.gpu.u32 [%0], %1;"
                         :: "l"(&g_rel_p[0]), "r"(nb) : "memory");
        } else {
            unsigned rel;
            do {
                asm volatile("ld.acquire.gpu.u32 %0, [%1];"
                             : "=r"(rel) : "l"(&g_rel_p[0]) : "memory");
            } while ((int)(rel - target) < 0);
        }
    }
    __syncthreads();
}

// tight global poll (one warp per counter per CTA)
__device__ __forceinline__ void poll_global(unsigned* cnt, unsigned tgt) {
    if ((threadIdx.x & 31) == 0) {
        unsigned v;
        do {
            asm volatile("ld.acquire.gpu.u32 %0, [%1];"
                         : "=r"(v) : "l"(cnt) : "memory");
        } while ((int)(v - tgt) < 0);
    }
    __syncwarp();
}

// ---------------- fast activations -------------------------------------------
__device__ __forceinline__ float sigf(float v) {
    return __fdividef(1.f, 1.f + __expf(-v));
}
__device__ __forceinline__ float tanhf_fast(float v) {
    float vc = fminf(fmaxf(v, -15.f), 15.f);
    float e  = __expf(-2.f * vc);
    return __fdividef(1.f - e, 1.f + e);
}

__device__ __forceinline__ uint pack2(float a, float b) {
    __half2 h = __floats2half2_rn(a, b);
    return *reinterpret_cast<uint*>(&h);
}

// ---------------- mma.sync m16n8k16 fp16 -> fp32 ------------------------------
struct Acc { float x, y, z, w; };

__device__ __forceinline__ void mma_f16(Acc& c, uint4 a, uint b0, uint b1) {
    asm volatile(
        "mma.sync.aligned.m16n8k16.row.col.f32.f16.f16.f32 "
        "{%0,%1,%2,%3}, {%4,%5,%6,%7}, {%8,%9}, {%0,%1,%2,%3};"
        : "+f"(c.x), "+f"(c.y), "+f"(c.z), "+f"(c.w)
        : "r"(a.x), "r"(a.y), "r"(a.z), "r"(a.w), "r"(b0), "r"(b1));
}

__device__ __forceinline__ void stacc1(float* r, int m0, int n0, Acc a) {
    r[m0 * 33 + n0]           = a.x;
    r[m0 * 33 + n0 + 1]       = a.y;
    r[(m0 + 8) * 33 + n0]     = a.z;
    r[(m0 + 8) * 33 + n0 + 1] = a.w;
}

// store 4 tiles (2 mtiles x 2 ntiles) into a partial buffer, columns of group q
__device__ __forceinline__ void stacc4(float* r, int q, int lane,
                                       Acc c00, Acc c01, Acc c10, Acc c11) {
    const int gid = lane >> 2, tig = lane & 3;
    const int nb  = q * 16 + tig * 2;
    stacc1(r, gid,      nb,     c00);
    stacc1(r, gid,      nb + 8, c01);
    stacc1(r, 16 + gid, nb,     c10);
    stacc1(r, 16 + gid, nb + 8, c11);
}

// 16-kstep MMA burst, A from SMEM
__device__ __forceinline__ void mma16(const uint4* A, const uint2* B,
                                      float* rbuf, int q, int lane) {
    Acc c00={0,0,0,0}, c01={0,0,0,0}, c10={0,0,0,0}, c11={0,0,0,0};
    #pragma unroll 8
    for (int k = 0; k < 16; ++k) {
        uint2 v0 = __ldcg(B + k * 32);
        uint2 v1 = __ldcg(B + k * 32 + 1024);
        uint4 a0 = A[k * 64];
        uint4 a1 = A[k * 64 + 32];
        mma_f16(c00, a0, v0.x, v0.y);
        mma_f16(c01, a0, v1.x, v1.y);
        mma_f16(c10, a1, v0.x, v0.y);
        mma_f16(c11, a1, v1.x, v1.y);
    }
    stacc4(rbuf, q, lane, c00, c01, c10, c11);
}
// 16-kstep MMA burst, A from global
__device__ __forceinline__ void mma16g(const uint4* A, const uint2* B,
                                       float* rbuf, int q, int lane) {
    Acc c00={0,0,0,0}, c01={0,0,0,0}, c10={0,0,0,0}, c11={0,0,0,0};
    #pragma unroll 8
    for (int k = 0; k < 16; ++k) {
        uint2 v0 = __ldcg(B + k * 32);
        uint2 v1 = __ldcg(B + k * 32 + 1024);
        uint4 a0 = __ldg(A + k * 64);
        uint4 a1 = __ldg(A + k * 64 + 32);
        mma_f16(c00, a0, v0.x, v0.y);
        mma_f16(c01, a0, v1.x, v1.y);
        mma_f16(c10, a1, v0.x, v0.y);
        mma_f16(c11, a1, v1.x, v1.y);
    }
    stacc4(rbuf, q, lane, c00, c01, c10, c11);
}
// 32-kstep MMA burst, A from SMEM
__device__ __forceinline__ void mma32s(const uint4* A, const uint2* B,
                                       float* rbuf, int q, int lane) {
    Acc c00={0,0,0,0}, c01={0,0,0,0}, c10={0,0,0,0}, c11={0,0,0,0};
    #pragma unroll 8
    for (int k = 0; k < 32; ++k) {
        uint2 v0 = __ldcg(B + k * 32);
        uint2 v1 = __ldcg(B + k * 32 + 1024);
        uint4 a0 = A[k * 64];
        uint4 a1 = A[k * 64 + 32];
        mma_f16(c00, a0, v0.x, v0.y);
        mma_f16(c01, a0, v1.x, v1.y);
        mma_f16(c10, a1, v0.x, v0.y);
        mma_f16(c11, a1, v1.x, v1.y);
    }
    stacc4(rbuf, q, lane, c00, c01, c10, c11);
}

// gate reduce + LSTM pointwise for one batch group (warps {q,q+2,q+4,q+6}).
// local = (wrp>>1)*32 + lane in [0,128): ul = local&7, b = q*16 + (local>>3).
// Sums buffers 0..3 plus e1, e2; packed 4B h store.
__device__ __forceinline__ void pointwise2(const float* sR, const float* b4,
                                           int e1, int e2, int q, int local,
                                           float& creg, float& hreg,
                                           uint2* seg, int ublk)
{
    const int ul = local & 7, b = q * 16 + (local >> 3);
    float g4[4];
    #pragma unroll
    for (int g = 0; g < 4; ++g) {
        int m = ul * 4 + g;
        float s = b4[g];
        #pragma unroll
        for (int p = 0; p < 4; ++p) s += sR[p * 1056 + m * 33 + b];
        s += sR[e1 * 1056 + m * 33 + b];
        s += sR[e2 * 1056 + m * 33 + b];
        g4[g] = s;
    }
    float cc = sigf(g4[1]) * creg + sigf(g4[0]) * tanhf_fast(g4[2]);
    creg = cc;
    hreg = sigf(g4[3]) * tanhf_fast(cc);
    uint hh = (uint)__half_as_ushort(__float2half_rn(hreg));
    uint hi = __shfl_xor_sync(0xffffffffu, hh, 1);     // partner unit ul^1
    if ((ul & 1) == 0) {
        int nt = b >> 3, pp = ul >> 1;
        int tp = ((b & 7) << 2) | pp;
        int ks = ublk >> 1, reg = ublk & 1;
        ((uint*)seg)[(((nt * 32 + ks) * 32 + tp) << 1) + reg] = (hi << 16) | hh;
    }
}

// -----------------------------------------------------------------------------
extern "C" __global__ void __launch_bounds__(NTHR, 1)
ar_encoder_v16(const float* __restrict__ x,     // [32,512,512]
               const float* __restrict__ Wih,   // [4][2048][1024]
               const float* __restrict__ Whh,   // [4][2048][512]
               const float* __restrict__ bih,   // [4][2048]
               const float* __restrict__ bhh,   // [4][2048]
               const float* __restrict__ Wfc,   // [512][1024]
               const float* __restrict__ bfc,   // [512]
               float* __restrict__ out)
{
    extern __shared__ char smem[];
    uint4* sA0 = (uint4*)(smem + SA0_OFF);
    uint4* sA1 = (uint4*)(smem + SA1_OFF);
    uint4* sM  = (uint4*)(smem + SM_OFF);
    float* sR  = (float*)(smem + SR_OFF);           // 8 x 1056 floats
    float* sBias = (float*)(smem + SB_OFF);         // [3][8][4]

    const int tid  = threadIdx.x;
    const int cta  = blockIdx.x;
    const int lane = tid & 31;
    const int wrp  = tid >> 5;
    const int gsz  = NCTA * NTHR;
    const int gtid = cta * NTHR + tid;

    const int d    = cta >> 6;
    const int ublk = cta & 63;
    const int j0   = ublk * 8;
    const int grp  = cta >> 5;           // CTA quarter group 0..3

    // ================= prologue phase 1 =====================================
    // (a) L0 weights (Wx + Wh0) -> sA0
    for (int i = tid; i < 32 * 512; i += NTHR) {
        int kp = i & 511, m = i >> 9;
        int grow = (m & 3) * 512 + j0 + (m >> 2);
        int k, ks; const float* p;
        if (kp < 256) { k = kp * 2; ks = k >> 4;
                        p = Wih + ((size_t)d * 2048 + grow) * 1024 + k; }
        else          { k = (kp - 256) * 2; ks = 32 + (k >> 4);
                        p = Whh + ((size_t)d * 2048 + grow) * 512 + k; }
        uint packed = pack2(p[0], p[1]);
        int kk = k & 15, mtile = m >> 4, mrow = m & 15;
        int tp  = ((mrow & 7) << 2) | ((kk >> 1) & 3);
        int reg = (mrow >> 3) | ((kk >> 3) << 1);
        ((uint*)sA0)[((ks * 2 + mtile) * 32 + tp) * 4 + reg] = packed;
    }
    // (b) Wp -> sA1 as TEMP A-fragments (K=512)
    for (int i = tid; i < 32 * 256; i += NTHR) {
        int kp = i & 255, m = i >> 8;
        int grow = (m & 3) * 512 + j0 + (m >> 2);
        int k = kp * 2;
        const float* p = Wih + ((size_t)d * 2048 + grow) * 1024 + 512 + k;
        uint packed = pack2(p[0], p[1]);
        int ks = k >> 4, kk = k & 15, mtile = m >> 4, mrow = m & 15;
        int tp  = ((mrow & 7) << 2) | ((kk >> 1) & 3);
        int reg = (mrow >> 3) | ((kk >> 3) << 1);
        ((uint*)sA1)[((ks * 2 + mtile) * 32 + tp) * 4 + reg] = packed;
    }
    // (c) Wfc -> B-fragments for the M GEMM
    for (uint i = gtid; i < 128u * 32u * 32u; i += gsz) {
        int ln = (int)(i & 31), ks = (int)((i >> 5) & 31), nt = (int)(i >> 10);
        int n  = nt * 8 + (ln >> 2);
        int o0 = ks * 16 + (ln & 3) * 2;
        uint2 v;
        v.x = pack2(Wfc[(size_t)o0 * 1024 + n],       Wfc[(size_t)(o0 + 1) * 1024 + n]);
        v.y = pack2(Wfc[(size_t)(o0 + 8) * 1024 + n], Wfc[(size_t)(o0 + 9) * 1024 + n]);
        g_wfcB[i] = v;
    }
    // (d) FC weights -> fp16 A fragments
    for (uint i = gtid; i < 512u * 512u; i += gsz) {
        int kp = (int)(i & 511u), row = (int)(i >> 9);
        int k = kp * 2;
        const float* p = Wfc + ((size_t)row << 10) + k;
        uint packed = pack2(p[0], p[1]);
        int rowblk = row >> 4, mrow = row & 15;
        int kstep = k >> 4, kk = k & 15;
        int tp  = ((mrow & 7) << 2) | ((kk >> 1) & 3);
        int reg = (mrow >> 3) | ((kk >> 3) << 1);
        ((uint*)g_afc)[(((rowblk * 64 + kstep) * 32) + tp) * 4 + reg] = packed;
    }
    // (e) input x -> fp16 B fragments, all t
    for (uint s = gtid; s < 512u * SEG_U2; s += gsz) {
        int ln = (int)(s & 31), ks = (int)((s >> 5) & 31), nt = (int)((s >> 10) & 3);
        int t  = (int)(s >> 12);
        int tig = ln & 3, gid = ln >> 2;
        int n = nt * 8 + gid, k0 = ks * 16 + tig * 2;
        const float* xp = x + ((size_t)n * 512 + t) * 512 + k0;
        uint2 v;
        v.x = pack2(xp[0], xp[1]);
        v.y = pack2(xp[8], xp[9]);
        g_xfrag[s] = v;
    }
    // (f) zero h0frag (both parities) + hist[0]
    {
        uint2 z = make_uint2(0, 0);
        for (uint i = gtid; i < 6u * SEG_U2; i += gsz) {
            if (i < 4u * SEG_U2) g_h0frag[i] = z;
            else                 g_h1hist[i - 4u * SEG_U2] = z;
        }
    }
    gridbar();

    // ================= prologue phase 2: M = Wp @ Wfc (fp16, hi only) =======
    {
        const int mtile = wrp & 1;
        uint* mhi = (uint*)sM;
        for (int nt = (wrp >> 1); nt < 128; nt += 6) {
            Acc c = {0, 0, 0, 0};
            const uint2* B = g_wfcB + (size_t)nt * 1024 + lane;
            const uint4* A = sA1 + mtile * 32 + lane;
            #pragma unroll 8
            for (int ks = 0; ks < 32; ++ks) {
                uint2 v = __ldcg(B + ks * 32);
                uint4 a = A[ks * 64];
                mma_f16(c, a, v.x, v.y);
            }
            int gid = lane >> 2, tig = lane & 3;
            int h = nt * 8 + tig * 2, kk = h & 15, kstep = h >> 4;
            int tp = ((gid & 7) << 2) | ((kk >> 1) & 3);
            int base = (((kstep * 2 + mtile) * 32) + tp) * 4;
            int rhib = (kk >> 3) << 1;
            mhi[base + rhib]     = pack2(c.x, c.y);
            mhi[base + rhib + 1] = pack2(c.z, c.w);
        }
    }
    __syncthreads();

    // (g) L1 weights: h0-part (64 ks) -> sA1, Whh-part (32 ks) -> g_w1h[cta]
    for (int i = tid; i < 32 * 768; i += NTHR) {
        int kp = i % 768, m = i / 768;
        int grow = (m & 3) * 512 + j0 + (m >> 2);
        int k = kp * 2; const float* p;
        if (k < 1024) p = Wih + ((size_t)(2 + d) * 2048 + grow) * 1024 + k;
        else          p = Whh + ((size_t)(2 + d) * 2048 + grow) * 512 + (k - 1024);
        uint packed = pack2(p[0], p[1]);
        int ks = k >> 4, kk = k & 15, mtile = m >> 4, mrow = m & 15;
        int tp  = ((mrow & 7) << 2) | ((kk >> 1) & 3);
        int reg = (mrow >> 3) | ((kk >> 3) << 1);
        if (ks < 64)
            ((uint*)sA1)[((ks * 2 + mtile) * 32 + tp) * 4 + reg] = packed;
        else
            ((uint*)(g_w1h + (size_t)cta * 2048))
                [(((ks - 64) * 2 + mtile) * 32 + tp) * 4 + reg] = packed;
    }

    // (h) biases (warp-uniform j), staged to SMEM
    if (tid < 256) {
        int ulw = tid >> 5, j = j0 + ulw;
        #pragma unroll
        for (int g = 0; g < 4; ++g) {
            float a0 = __ldg(bih + (size_t)d * 2048 + g * 512 + j)
                     + __ldg(bhh + (size_t)d * 2048 + g * 512 + j);
            float a1 = __ldg(bih + (size_t)(2 + d) * 2048 + g * 512 + j)
                     + __ldg(bhh + (size_t)(2 + d) * 2048 + g * 512 + j);
            int grow = g * 512 + j;
            const float* wp = Wih + ((size_t)d * 2048 + grow) * 1024 + 512;
            float p = 0.f;
            for (int o = lane; o < 512; o += 32) p += wp[o] * __ldg(bfc + o);
            #pragma unroll
            for (int s = 16; s; s >>= 1) p += __shfl_xor_sync(0xffffffffu, p, s);
            if (lane == 0) {
                sBias[(0 * 8 + ulw) * 4 + g] = a0;
                sBias[(1 * 8 + ulw) * 4 + g] = a0 + p;
                sBias[(2 * 8 + ulw) * 4 + g] = a1;
            }
        }
    }
    // zero partial buffers
    for (int i = tid; i < 8 * 1056; i += NTHR) sR[i] = 0.f;
    __syncthreads();

    // group identity + bias load with pointwise thread map
    const int q    = wrp & 1;            // batch group 0/1
    const int role = wrp >> 1;           // 0-3 late, 4 early, 5 x/Whh1
    const int nb   = q * 2048;           // B column offset for this group
    const int local = (wrp < 8) ? ((wrp >> 1) * 32 + lane) : 0;
    float bA0[4], bB0[4], bA1[4];
    {
        int ul = local & 7;
        #pragma unroll
        for (int g = 0; g < 4; ++g) {
            bA0[g] = sBias[(0 * 8 + ul) * 4 + g];
            bB0[g] = sBias[(1 * 8 + ul) * 4 + g];
            bA1[g] = sBias[(2 * 8 + ul) * 4 + g];
        }
    }

    // (i) prime buffer 5 with Wx @ x(0) (per group)
    if (role == 5) {
        mma32s(sA0 + lane, g_xfrag + nb + lane, sR + 5 * 1056, q, lane);
    }
    __syncthreads();

    // ================= main loop: two decoupled batch-group chains ===========
    float creg0 = 0.f, hreg0 = 0.f, creg1 = 0.f, hreg1 = 0.f;
    const uint4* W1h = g_w1h + (size_t)cta * 2048;

    for (int t = 0; t < 512; ++t) {
        const int pold = t & 1, pnew = pold ^ 1;
        const uint2* histT = g_h1hist + (size_t)t * 2 * SEG_U2;

        // ---- A-window: h0(t) for group q ----
        if (role < 4) {                      // late: M@h1cat(t-1), quarter=role
            poll_global(&g_cnt_p[(8 + role * 2 + q) * 32], 32u * (uint)t);
            const int km = role * 16;
            mma16(sM + km * 64 + lane,
                  histT + (size_t)(km >> 5) * SEG_U2 + (km & 31) * 32 + nb + lane,
                  sR + role * 1056, q, lane);
        } else if (role == 4) {              // early: Wh0 @ h0(t-1), 32 ks (no wait)
            mma32s(sA0 + 2048 + lane,
                   g_h0frag + (size_t)(pold * 2 + d) * SEG_U2 + nb + lane,
                   sR + 4 * 1056, q, lane);
        } else {                             // x warp: Wx @ x(t+1), 32 ks
            if (t < 511)
                mma32s(sA0 + lane,
                       g_xfrag + (size_t)(t + 1) * SEG_U2 + nb + lane,
                       sR + (5 + ((t + 1) & 1)) * 1056, q, lane);
        }
        BARG(q);
        if (wrp < 8)
            pointwise2(sR, t == 0 ? bA0 : bB0, 4, 5 + (t & 1), q, local,
                       creg0, hreg0,
                       g_h0frag + (size_t)(pnew * 2 + d) * SEG_U2, ublk);
        BARG(q);
        if (wrp == q && lane == 0)
            asm volatile("red.add.release.gpu.u32 [%0], %1;"
                         :: "l"(&g_cnt_p[(grp * 2 + q) * 32]), "r"(1u) : "memory");

        // ---- B-window: h1(t) for group q ----
        if (role < 4) {                      // late: W1 @ h0cat(t), quarter=role
            poll_global(&g_cnt_p[(role * 2 + q) * 32], 32u * (uint)(t + 1));
            const int km = role * 16;
            mma16(sA1 + km * 64 + lane,
                  g_h0frag + (size_t)(pnew * 2 + (km >> 5)) * SEG_U2
                           + (km & 31) * 32 + nb + lane,
                  sR + role * 1056, q, lane);
        } else if (role == 4) {              // Whh1 ks 0-15 (no wait: inherited)
            mma16g(W1h + lane,
                   histT + (size_t)d * SEG_U2 + nb + lane,
                   sR + 4 * 1056, q, lane);
        } else {                             // Whh1 ks 16-31
            mma16g(W1h + 16 * 64 + lane,
                   histT + (size_t)d * SEG_U2 + 16 * 32 + nb + lane,
                   sR + 7 * 1056, q, lane);
        }
        BARG(q);
        if (wrp < 8)
            pointwise2(sR, bA1, 4, 7, q, local,
                       creg1, hreg1,
                       g_h1hist + ((size_t)(t + 1) * 2 + d) * SEG_U2, ublk);
        BARG(q);
        if (wrp == q && lane == 0)
            asm volatile("red.add.release.gpu.u32 [%0], %1;"
                         :: "l"(&g_cnt_p[(8 + grp * 2 + q) * 32]), "r"(1u) : "memory");
    }

    // ================= epilogue: h_n, c_n from registers =====================
    if (wrp < 8) {
        const size_t HN = 8388608ull;             // 32*512*512
        const size_t CN = HN + 65536ull;
        int ul = local & 7, b = q * 16 + (local >> 3);
        int j = j0 + ul;
        out[HN + ((size_t)((0 + d) * 32 + b)) * 512 + j] = hreg0;
        out[HN + ((size_t)((2 + d) * 32 + b)) * 512 + j] = hreg1;
        out[CN + ((size_t)((0 + d) * 32 + b)) * 512 + j] = creg0;
        out[CN + ((size_t)((2 + d) * 32 + b)) * 512 + j] = creg1;
    }

    // ================= batched FC over all t =================================
    if (tid == 0) {                      // wait for ALL h1 history (8 counters)
        #pragma unroll
        for (int c = 8; c < 16; ++c) {
            unsigned v;
            for (;;) {
                asm volatile("ld.acquire.gpu.u32 %0, [%1];"
                             : "=r"(v) : "l"(&g_cnt_p[c * 32]) : "memory");
                if ((int)(v - 16384u) >= 0) break;
                __nanosleep(80);
            }
        }
    }
    __syncthreads();
    {
        float* sRw = sR + wrp * 528;                 // [16][33] per warp
        for (int tt = 0; tt < 4; ++tt) {
            const int t = cta + tt * 128;
            const uint2* Bbase = g_h1hist + (size_t)(t + 1) * 2 * SEG_U2;
            for (int rb = wrp; rb < 32; rb += 12) {
                const uint4* A = g_afc + (size_t)(rb * 64) * 32 + lane;
                Acc c0={0,0,0,0}, c1={0,0,0,0}, c2={0,0,0,0}, c3={0,0,0,0};
                #pragma unroll 4
                for (int ks = 0; ks < 64; ++ks) {
                    const uint2* B = Bbase + (size_t)(ks >> 5) * SEG_U2
                                   + (ks & 31) * 32 + lane;
                    uint2 v0 = __ldcg(B);
                    uint2 v1 = __ldcg(B + 1024);
                    uint2 v2 = __ldcg(B + 2048);
                    uint2 v3 = __ldcg(B + 3072);
                    uint4 a  = __ldg(A + ks * 32);
                    mma_f16(c0, a, v0.x, v0.y);
                    mma_f16(c1, a, v1.x, v1.y);
                    mma_f16(c2, a, v2.x, v2.y);
                    mma_f16(c3, a, v3.x, v3.y);
                }
                const int gid = lane >> 2, tig = lane & 3;
                stacc1(sRw, gid, 0  + tig * 2, c0);
                stacc1(sRw, gid, 8  + tig * 2, c1);
                stacc1(sRw, gid, 16 + tig * 2, c2);
                stacc1(sRw, gid, 24 + tig * 2, c3);
                __syncwarp();
                float* op = out + ((size_t)lane * 512 + t) * 512 + rb * 16;
                #pragma unroll
                for (int qq = 0; qq < 4; ++qq) {
                    float v0 = sRw[(qq*4+0) * 33 + lane] + __ldg(bfc + rb*16 + qq*4+0);
                    float v1 = sRw[(qq*4+1) * 33 + lane] + __ldg(bfc + rb*16 + qq*4+1);
                    float v2 = sRw[(qq*4+2) * 33 + lane] + __ldg(bfc + rb*16 + qq*4+2);
                    float v3 = sRw[(qq*4+3) * 33 + lane] + __ldg(bfc + rb*16 + qq*4+3);
                    *(float4*)(op + qq * 4) = make_float4(v0, v1, v2, v3);
                }
                __syncwarp();
            }
        }
    }

    // ================= reset dataflow counters for next launch ===============
    gridbar();
    if (cta == 0 && tid == 0) {
        #pragma unroll
        for (int c = 0; c < 16; ++c)
            asm volatile("st.relaxed.gpu.u32 [%0], %1;"
                         :: "l"(&g_cnt_p[c * 32]), "r"(0u) : "memory");
    }
}

extern "C" void kernel_launch(void* const* d_in, const int* in_sizes, int n_in,
                              void* d_out, int out_size) {
    (void)in_sizes; (void)n_in; (void)out_size;
    const float* x   = (const float*)d_in[0];
    const float* Wih = (const float*)d_in[2];
    const float* Whh = (const float*)d_in[3];
    const float* bih = (const float*)d_in[4];
    const float* bhh = (const float*)d_in[5];
    const float* Wfc = (const float*)d_in[6];
    const float* bfc = (const float*)d_in[7];
    cudaFuncSetAttribute(ar_encoder_v16,
                         cudaFuncAttributeMaxDynamicSharedMemorySize, SMEM_BYTES);
    ar_encoder_v16<<<NCTA, NTHR, SMEM_BYTES>>>(x, Wih, Whh, bih, bhh, Wfc, bfc,
                                               (float*)d_out);
}